// round 10
// baseline (speedup 1.0000x reference)
#include <cuda_runtime.h>
#include <cstdint>

#define NN 524288
#define ROWS_PB 256
#define GRID (NN / ROWS_PB)   // 2048 blocks, 512 threads, warp owns 16 rows
#define DD 64
#define HH 128
#define EE 8
#define AA 18
#define BN_EPS 1e-5f
#define MARGIN_TH 1e-4f

typedef unsigned long long u64;
typedef uint32_t u32;

__device__ __forceinline__ u64 pk2(float lo, float hi) {
    u64 r; asm("mov.b64 %0,{%1,%2};" : "=l"(r) : "f"(lo), "f"(hi)); return r;
}
__device__ __forceinline__ void upk2(u64 v, float& lo, float& hi) {
    asm("mov.b64 {%0,%1},%2;" : "=f"(lo), "=f"(hi) : "l"(v));
}
__device__ __forceinline__ void ffma2(u64& d, u64 a, u64 b) {
    asm("fma.rn.f32x2 %0,%1,%2,%0;" : "+l"(d) : "l"(a), "l"(b));
}
__device__ __forceinline__ u64 add2(u64 a, u64 b) {
    u64 r; asm("add.rn.f32x2 %0,%1,%2;" : "=l"(r) : "l"(a), "l"(b)); return r;
}
__device__ __forceinline__ void split_tf32(float v, u32& hi, u32& lo) {
    asm("cvt.rna.tf32.f32 %0, %1;" : "=r"(hi) : "f"(v));
    float r = v - __uint_as_float(hi);
    asm("cvt.rna.tf32.f32 %0, %1;" : "=r"(lo) : "f"(r));
}
__device__ __forceinline__ void mma8(float* d, const u32* a, u32 b0, u32 b1) {
    asm("mma.sync.aligned.m16n8k8.row.col.f32.tf32.tf32.f32 "
        "{%0,%1,%2,%3},{%4,%5,%6,%7},{%8,%9},{%0,%1,%2,%3};"
        : "+f"(d[0]), "+f"(d[1]), "+f"(d[2]), "+f"(d[3])
        : "r"(a[0]), "r"(a[1]), "r"(a[2]), "r"(a[3]), "r"(b0), "r"(b1));
}

// slot permutation: within each 8-k group, (k, k+4) become adjacent slots
__device__ __forceinline__ int kslot(int k) {
    return (k >> 3) * 8 + (k & 3) * 2 + ((k & 7) >> 2);
}

// ---- smem layout (float offsets) ----
#define WHI_OFF   0        // [128 j][68]  k-permuted tf32-hi
#define WLO_OFF   8704     // [128 j][68]  tf32-lo
#define XS_OFF    17408    // [256 r][68]  fp32, k-permuted
#define SBW_OFF   34816    // [128 j][12]: w2t[0..7], s, b, pad2
#define B2S_OFF   36352
#define WES_OFF   36368    // [8 e][18 a][64] stride 1156
#define BEST_OFF  46192    // 256 ints
#define SMEM_FLOATS 46448
#define WE_STRIDE 1156

__global__ __launch_bounds__(512, 1) void moe_fused(
    const float* __restrict__ X,  const float* __restrict__ W1, const float* __restrict__ b1,
    const float* __restrict__ gamma, const float* __restrict__ beta,
    const float* __restrict__ rmean, const float* __restrict__ rvar,
    const float* __restrict__ W2, const float* __restrict__ b2, const float* __restrict__ We,
    float* __restrict__ out, float* __restrict__ ret)
{
    extern __shared__ float sm[];
    float* whi_s = sm + WHI_OFF;
    float* wlo_s = sm + WLO_OFF;
    float* xs    = sm + XS_OFF;
    float* sbw_s = sm + SBW_OFF;
    float* b2s   = sm + B2S_OFF;
    float* wes   = sm + WES_OFF;
    int*   best_s = (int*)(sm + BEST_OFF);

    const int tid = threadIdx.x;
    const int row0 = blockIdx.x * ROWS_PB;

    // ================= staging =================
    #pragma unroll
    for (int i = 0; i < 16; i++) {
        int idx = tid + 512 * i;           // < 8192
        int j = idx >> 6, k = idx & 63;
        float w = W1[idx];
        u32 hi, lo; split_tf32(w, hi, lo);
        int s = kslot(k);
        whi_s[j * 68 + s] = __uint_as_float(hi);
        wlo_s[j * 68 + s] = __uint_as_float(lo);
    }
    #pragma unroll
    for (int i = 0; i < 8; i++) {
        int idx = tid + 512 * i;           // < 4096 float4
        int r = idx >> 4, kq = idx & 15;
        float4 v = ((const float4*)X)[(size_t)(row0 + r) * 16 + kq];
        xs[r * 68 + kslot(4 * kq + 0)] = v.x;
        xs[r * 68 + kslot(4 * kq + 1)] = v.y;
        xs[r * 68 + kslot(4 * kq + 2)] = v.z;
        xs[r * 68 + kslot(4 * kq + 3)] = v.w;
    }
    {
        const float4* src = (const float4*)We;
        float4* dst = (float4*)wes;
        #pragma unroll
        for (int i = 0; i < 5; i++) {
            int idx = tid + 512 * i;
            if (idx < 2304) {
                int e = idx / 288, r = idx % 288;
                dst[e * (WE_STRIDE / 4) + r] = src[idx];
            }
        }
    }
    #pragma unroll
    for (int i = 0; i < 2; i++) {
        int idx = tid + 512 * i;           // < 1024
        int j = idx >> 3, e = idx & 7;
        sbw_s[j * 12 + e] = W2[e * HH + j];
    }
    if (tid < HH) {
        int j = tid;
        float s = gamma[j] * rsqrtf(rvar[j] + BN_EPS);
        sbw_s[j * 12 + 8] = s;
        sbw_s[j * 12 + 9] = s * (b1[j] - rmean[j]) + beta[j];
    }
    if (tid < EE) b2s[tid] = b2[tid];
    __syncthreads();

    // ================= gating via 3xTF32 mma =================
    const int w    = tid >> 5;
    const int lane = tid & 31;
    const int gid  = lane >> 2;
    const int tig  = lane & 3;
    const int lr0  = w * 16 + gid;
    const int lr1  = lr0 + 8;

    // ---- A fragments: split ONCE (64 regs) ----
    u32 ah[8][4], al[8][4];
    {
        const float* xr0 = xs + lr0 * 68;
        const float* xr1 = xs + lr1 * 68;
        #pragma unroll
        for (int ks = 0; ks < 8; ks++) {
            float2 xa = *(const float2*)(xr0 + ks * 8 + tig * 2);
            float2 xb = *(const float2*)(xr1 + ks * 8 + tig * 2);
            split_tf32(xa.x, ah[ks][0], al[ks][0]);
            split_tf32(xb.x, ah[ks][1], al[ks][1]);
            split_tf32(xa.y, ah[ks][2], al[ks][2]);
            split_tf32(xb.y, ah[ks][3], al[ks][3]);
        }
    }

    u64 plog[2][4];
    #pragma unroll
    for (int r = 0; r < 2; r++)
        #pragma unroll
        for (int q = 0; q < 4; q++) plog[r][q] = pk2(0.f, 0.f);

    #pragma unroll 1
    for (int t = 0; t < 16; t++) {
        // 3 independent accumulation chains (one per tf32 pass)
        float da[4] = {0.f, 0.f, 0.f, 0.f};
        float db[4] = {0.f, 0.f, 0.f, 0.f};
        float dc[4] = {0.f, 0.f, 0.f, 0.f};
        const float* bh_base = whi_s + (t * 8 + gid) * 68 + tig * 2;
        const float* bl_base = wlo_s + (t * 8 + gid) * 68 + tig * 2;
        #pragma unroll
        for (int ks = 0; ks < 8; ks++) {
            float2 bh = *(const float2*)(bh_base + ks * 8);
            float2 bl = *(const float2*)(bl_base + ks * 8);
            u32 bh0 = __float_as_uint(bh.x), bh1 = __float_as_uint(bh.y);
            u32 bl0 = __float_as_uint(bl.x), bl1 = __float_as_uint(bl.y);
            mma8(da, ah[ks], bh0, bh1);
            mma8(db, ah[ks], bl0, bl1);
            mma8(dc, al[ks], bh0, bh1);
        }
        float d0 = da[0] + db[0] + dc[0];
        float d1 = da[1] + db[1] + dc[1];
        float d2 = da[2] + db[2] + dc[2];
        float d3 = da[3] + db[3] + dc[3];

        // epilogue: BN + ReLU + partial logits
        int j0 = t * 8 + tig * 2;
        const float* rec0 = sbw_s + j0 * 12;
        const float* rec1 = rec0 + 12;
        float2 sb0 = *(const float2*)(rec0 + 8);
        float2 sb1 = *(const float2*)(rec1 + 8);
        float h00 = fmaxf(fmaf(sb0.x, d0, sb0.y), 0.f);
        float h01 = fmaxf(fmaf(sb1.x, d1, sb1.y), 0.f);
        float h10 = fmaxf(fmaf(sb0.x, d2, sb0.y), 0.f);
        float h11 = fmaxf(fmaf(sb1.x, d3, sb1.y), 0.f);
        u64 hb00 = pk2(h00, h00), hb01 = pk2(h01, h01);
        u64 hb10 = pk2(h10, h10), hb11 = pk2(h11, h11);
        ulonglong2 wa0 = *(const ulonglong2*)(rec0);
        ulonglong2 wa1 = *(const ulonglong2*)(rec0 + 4);
        ulonglong2 wb0 = *(const ulonglong2*)(rec1);
        ulonglong2 wb1 = *(const ulonglong2*)(rec1 + 4);
        ffma2(plog[0][0], hb00, wa0.x);
        ffma2(plog[0][1], hb00, wa0.y);
        ffma2(plog[0][2], hb00, wa1.x);
        ffma2(plog[0][3], hb00, wa1.y);
        ffma2(plog[0][0], hb01, wb0.x);
        ffma2(plog[0][1], hb01, wb0.y);
        ffma2(plog[0][2], hb01, wb1.x);
        ffma2(plog[0][3], hb01, wb1.y);
        ffma2(plog[1][0], hb10, wa0.x);
        ffma2(plog[1][1], hb10, wa0.y);
        ffma2(plog[1][2], hb10, wa1.x);
        ffma2(plog[1][3], hb10, wa1.y);
        ffma2(plog[1][0], hb11, wb0.x);
        ffma2(plog[1][1], hb11, wb0.y);
        ffma2(plog[1][2], hb11, wb1.x);
        ffma2(plog[1][3], hb11, wb1.y);
    }

    // quad reduce
    #pragma unroll
    for (int r = 0; r < 2; r++)
        #pragma unroll
        for (int q = 0; q < 4; q++) {
            plog[r][q] = add2(plog[r][q], __shfl_xor_sync(0xffffffffu, plog[r][q], 1));
            plog[r][q] = add2(plog[r][q], __shfl_xor_sync(0xffffffffu, plog[r][q], 2));
        }

    if (tig == 0) {
        #pragma unroll 1
        for (int r = 0; r < 2; r++) {
            int lrow = r ? lr1 : lr0;
            int grow = row0 + lrow;
            float lf[8];
            upk2(plog[r][0], lf[0], lf[1]);
            upk2(plog[r][1], lf[2], lf[3]);
            upk2(plog[r][2], lf[4], lf[5]);
            upk2(plog[r][3], lf[6], lf[7]);
            #pragma unroll
            for (int e = 0; e < 8; e++) lf[e] += b2s[e];

            int best = 0; float bv = lf[0]; float sv = -1e30f;
            #pragma unroll
            for (int e = 1; e < 8; e++) {
                if (lf[e] > bv) { sv = bv; bv = lf[e]; best = e; }
                else if (lf[e] > sv) { sv = lf[e]; }
            }

            if (bv - sv < MARGIN_TH) {
                float lf2[8];
                #pragma unroll
                for (int e = 0; e < 8; e++) lf2[e] = b2s[e];
                const float* xg = X + (size_t)grow * DD;
                #pragma unroll 1
                for (int j = 0; j < HH; j++) {
                    const float* wh = whi_s + j * 68;
                    const float* wl = wlo_s + j * 68;
                    float dot = 0.f;
                    #pragma unroll
                    for (int s = 0; s < 64; s++) {
                        int k = (s >> 3) * 8 + ((s & 7) >> 1) + (s & 1) * 4;
                        dot += (wh[s] + wl[s]) * __ldg(xg + k);
                    }
                    float y = fmaxf(fmaf(sbw_s[j * 12 + 8], dot, sbw_s[j * 12 + 9]), 0.f);
                    #pragma unroll
                    for (int e = 0; e < 8; e++) lf2[e] += y * sbw_s[j * 12 + e];
                }
                best = 0; float bv2 = lf2[0];
                #pragma unroll
                for (int e = 1; e < 8; e++)
                    if (lf2[e] > bv2) { bv2 = lf2[e]; best = e; }
            }

            float rv[8];
            #pragma unroll
            for (int e = 0; e < 8; e++) rv[e] = (e == best) ? 1.0f : 0.0f;
            float4* pr = (float4*)(ret + (size_t)grow * EE);
            pr[0] = make_float4(rv[0], rv[1], rv[2], rv[3]);
            pr[1] = make_float4(rv[4], rv[5], rv[6], rv[7]);
            best_s[lrow] = best;
        }
    }
    __syncthreads();

    // ================= expert GEMV: 2 threads per row (fp32 exact) =================
    {
        const u64 Z = pk2(0.f, 0.f);
        int lrow = tid >> 1;
        int half = tid & 1;
        int grow = row0 + lrow;
        int best = best_s[lrow];

        u64 xq[32];
        const ulonglong2* pg = (const ulonglong2*)(X + (size_t)grow * DD);
        #pragma unroll
        for (int i = 0; i < 16; i++) {
            ulonglong2 t = pg[i];
            xq[2 * i] = t.x; xq[2 * i + 1] = t.y;
        }

        const ulonglong2* pe = (const ulonglong2*)(wes + best * WE_STRIDE);
        float* orow = out + (size_t)grow * AA;
        int aStart = half * 9;
        #pragma unroll
        for (int ai = 0; ai < 9; ai++) {
            int a = aStart + ai;
            u64 a0 = Z, a1 = Z, a2 = Z, a3 = Z;
            #pragma unroll
            for (int m = 0; m < 8; m++) {
                ulonglong2 wv = pe[a * 16 + 2 * m];
                ulonglong2 vv = pe[a * 16 + 2 * m + 1];
                ffma2(a0, wv.x, xq[4 * m + 0]);
                ffma2(a1, wv.y, xq[4 * m + 1]);
                ffma2(a2, vv.x, xq[4 * m + 2]);
                ffma2(a3, vv.y, xq[4 * m + 3]);
            }
            u64 s = add2(add2(a0, a1), add2(a2, a3));
            float lo, hi; upk2(s, lo, hi);
            orow[a] = lo + hi;
        }
    }
}

extern "C" void kernel_launch(void* const* d_in, const int* in_sizes, int n_in,
                              void* d_out, int out_size) {
    const float* X     = (const float*)d_in[0];
    const float* W1    = (const float*)d_in[1];
    const float* b1    = (const float*)d_in[2];
    const float* gamma = (const float*)d_in[3];
    const float* beta  = (const float*)d_in[4];
    const float* rmean = (const float*)d_in[5];
    const float* rvar  = (const float*)d_in[6];
    const float* W2    = (const float*)d_in[7];
    const float* b2    = (const float*)d_in[8];
    const float* We    = (const float*)d_in[9];

    float* out = (float*)d_out;                    // [N, A]
    float* ret = out + (size_t)NN * AA;            // [N, E]

    size_t smem = SMEM_FLOATS * sizeof(float);
    static bool attr_set = false;
    if (!attr_set) {
        cudaFuncSetAttribute(moe_fused, cudaFuncAttributeMaxDynamicSharedMemorySize, (int)smem);
        attr_set = true;
    }
    moe_fused<<<GRID, 512, smem>>>(X, W1, b1, gamma, beta, rmean, rvar, W2, b2, We, out, ret);
}

// round 12
// speedup vs baseline: 2.0524x; 2.0524x over previous
#include <cuda_runtime.h>

#define NN 524288
#define ROWS_PB 384
#define GRID ((NN + ROWS_PB - 1) / ROWS_PB)   // 1366
#define DD 64
#define HH 128
#define EE 8
#define AA 18
#define BN_EPS 1e-5f

typedef unsigned long long u64;

__device__ __forceinline__ u64 pk2(float lo, float hi) {
    u64 r; asm("mov.b64 %0,{%1,%2};" : "=l"(r) : "f"(lo), "f"(hi)); return r;
}
__device__ __forceinline__ void upk2(u64 v, float& lo, float& hi) {
    asm("mov.b64 {%0,%1},%2;" : "=f"(lo), "=f"(hi) : "l"(v));
}
__device__ __forceinline__ void ffma2(u64& d, u64 a, u64 b) {
    asm("fma.rn.f32x2 %0,%1,%2,%0;" : "+l"(d) : "l"(a), "l"(b));
}
__device__ __forceinline__ u64 add2(u64 a, u64 b) {
    u64 r; asm("add.rn.f32x2 %0,%1,%2;" : "=l"(r) : "l"(a), "l"(b)); return r;
}

// smem layout (floats):
//   w1s [0, 8192)        W1 row-major [H][D]
//   w2t [8192, 9216)     W2 transposed [H][E]
//   sbs [9216, 9472)     (scale,bias) per j
//   b2s [9472, 9488)
//   wes [9488, ...)      We flat, stride 1156/expert
#define WE_STRIDE 1156
#define SMEM_FLOATS (9488 + EE * WE_STRIDE)

__global__ __launch_bounds__(128, 2) void moe_fused(
    const float* __restrict__ X,  const float* __restrict__ W1, const float* __restrict__ b1,
    const float* __restrict__ gamma, const float* __restrict__ beta,
    const float* __restrict__ rmean, const float* __restrict__ rvar,
    const float* __restrict__ W2, const float* __restrict__ b2, const float* __restrict__ We,
    float* __restrict__ out, float* __restrict__ ret)
{
    extern __shared__ float sm[];
    float* w1s = sm;
    float* w2t = sm + 8192;
    float* sbs = sm + 9216;
    float* b2s = sm + 9472;
    float* wes = sm + 9488;

    const int tid = threadIdx.x;

    // ---- stage weights (128 threads) ----
    {   const float4* src = (const float4*)W1;
        float4* dst = (float4*)w1s;
        #pragma unroll
        for (int i = 0; i < 16; i++) dst[tid + 128 * i] = src[tid + 128 * i];
    }
    {   const float4* src = (const float4*)We;
        float4* dst = (float4*)wes;
        #pragma unroll
        for (int i = 0; i < 18; i++) {
            int idx = tid + 128 * i;
            int e = idx / 288, r = idx % 288;
            dst[e * (WE_STRIDE / 4) + r] = src[idx];
        }
    }
    #pragma unroll
    for (int i = 0; i < 8; i++) {
        int idx = tid + 128 * i;
        int j = idx >> 3, e = idx & 7;
        w2t[idx] = W2[e * HH + j];
    }
    {
        int j = tid;
        float s = gamma[j] * rsqrtf(rvar[j] + BN_EPS);
        sbs[2 * j]     = s;
        sbs[2 * j + 1] = s * (b1[j] - rmean[j]) + beta[j];
    }
    if (tid < EE) b2s[tid] = b2[tid];
    __syncthreads();

    const int base = blockIdx.x * ROWS_PB + tid;
    int rowi[3];
    bool valid[3];
    #pragma unroll
    for (int rr = 0; rr < 3; rr++) {
        int r = base + rr * 128;
        valid[rr] = (r < NN);
        rowi[rr] = valid[rr] ? r : (NN - 1);
    }

    // ---- x for 3 rows in regs ----
    u64 xp0[32], xp1[32], xp2[32];
    {
        const ulonglong2* p0 = (const ulonglong2*)(X + (size_t)rowi[0] * DD);
        const ulonglong2* p1 = (const ulonglong2*)(X + (size_t)rowi[1] * DD);
        const ulonglong2* p2 = (const ulonglong2*)(X + (size_t)rowi[2] * DD);
        #pragma unroll
        for (int i = 0; i < 16; i++) {
            ulonglong2 t0 = p0[i]; xp0[2 * i] = t0.x; xp0[2 * i + 1] = t0.y;
            ulonglong2 t1 = p1[i]; xp1[2 * i] = t1.x; xp1[2 * i + 1] = t1.y;
            ulonglong2 t2 = p2[i]; xp2[2 * i] = t2.x; xp2[2 * i + 1] = t2.y;
        }
    }

    const u64 Z = pk2(0.f, 0.f);

    u64 lg0[4], lg1[4], lg2[4];
    #pragma unroll
    for (int k = 0; k < 4; k++) {
        u64 b2p = pk2(b2s[2 * k], b2s[2 * k + 1]);
        lg0[k] = b2p; lg1[k] = b2p; lg2[k] = b2p;
    }

    // ---- gating: uniform W1 load feeds 3 rows; unroll 2 for latency overlap ----
    #pragma unroll 2
    for (int j = 0; j < HH; j++) {
        const ulonglong2* pw = (const ulonglong2*)(w1s + j * DD);
        u64 a0 = Z, a1 = Z, c0 = Z, c1 = Z, d0 = Z, d1 = Z;
        #pragma unroll
        for (int i = 0; i < 16; i++) {
            ulonglong2 w = pw[i];
            ffma2(a0, w.x, xp0[2 * i]);
            ffma2(c0, w.x, xp1[2 * i]);
            ffma2(d0, w.x, xp2[2 * i]);
            ffma2(a1, w.y, xp0[2 * i + 1]);
            ffma2(c1, w.y, xp1[2 * i + 1]);
            ffma2(d1, w.y, xp2[2 * i + 1]);
        }
        u64 s0 = add2(a0, a1), s1 = add2(c0, c1), s2 = add2(d0, d1);
        float e0, f0, e1, f1, e2, f2;
        upk2(s0, e0, f0); upk2(s1, e1, f1); upk2(s2, e2, f2);
        float dot0 = e0 + f0, dot1 = e1 + f1, dot2 = e2 + f2;

        float2 sb = ((const float2*)sbs)[j];
        float y0 = fmaxf(fmaf(sb.x, dot0, sb.y), 0.f);
        float y1 = fmaxf(fmaf(sb.x, dot1, sb.y), 0.f);
        float y2 = fmaxf(fmaf(sb.x, dot2, sb.y), 0.f);
        u64 yb0 = pk2(y0, y0), yb1 = pk2(y1, y1), yb2 = pk2(y2, y2);

        const ulonglong2* pw2 = (const ulonglong2*)(w2t + j * EE);
        ulonglong2 q0 = pw2[0], q1 = pw2[1];
        ffma2(lg0[0], q0.x, yb0);
        ffma2(lg1[0], q0.x, yb1);
        ffma2(lg2[0], q0.x, yb2);
        ffma2(lg0[1], q0.y, yb0);
        ffma2(lg1[1], q0.y, yb1);
        ffma2(lg2[1], q0.y, yb2);
        ffma2(lg0[2], q1.x, yb0);
        ffma2(lg1[2], q1.x, yb1);
        ffma2(lg2[2], q1.x, yb2);
        ffma2(lg0[3], q1.y, yb0);
        ffma2(lg1[3], q1.y, yb1);
        ffma2(lg2[3], q1.y, yb2);
    }

    // ---- per row: argmax + one-hot + expert GEMV ----
    #pragma unroll 1
    for (int rr = 0; rr < 3; rr++) {
        if (!valid[rr]) continue;
        const u64* lg = (rr == 0) ? lg0 : (rr == 1) ? lg1 : lg2;
        const u64* xp = (rr == 0) ? xp0 : (rr == 1) ? xp1 : xp2;
        const int row = rowi[rr];

        float lf[8];
        upk2(lg[0], lf[0], lf[1]);
        upk2(lg[1], lf[2], lf[3]);
        upk2(lg[2], lf[4], lf[5]);
        upk2(lg[3], lf[6], lf[7]);
        int best = 0; float bv = lf[0];
        #pragma unroll
        for (int e = 1; e < 8; e++) if (lf[e] > bv) { bv = lf[e]; best = e; }

        float rv[8];
        #pragma unroll
        for (int e = 0; e < 8; e++) rv[e] = (e == best) ? 1.0f : 0.0f;
        float4* pr = (float4*)(ret + (size_t)row * EE);
        pr[0] = make_float4(rv[0], rv[1], rv[2], rv[3]);
        pr[1] = make_float4(rv[4], rv[5], rv[6], rv[7]);

        const ulonglong2* pe = (const ulonglong2*)(wes + best * WE_STRIDE);
        float* orow = out + (size_t)row * AA;
        #pragma unroll
        for (int a = 0; a < AA; a++) {
            u64 a0 = Z, a1 = Z, a2 = Z, a3 = Z;
            #pragma unroll
            for (int m = 0; m < 8; m++) {
                ulonglong2 w = pe[a * 16 + 2 * m];
                ulonglong2 v = pe[a * 16 + 2 * m + 1];
                ffma2(a0, w.x, xp[4 * m + 0]);
                ffma2(a1, w.y, xp[4 * m + 1]);
                ffma2(a2, v.x, xp[4 * m + 2]);
                ffma2(a3, v.y, xp[4 * m + 3]);
            }
            u64 s = add2(add2(a0, a1), add2(a2, a3));
            float lo, hi; upk2(s, lo, hi);
            orow[a] = lo + hi;
        }
    }
}

extern "C" void kernel_launch(void* const* d_in, const int* in_sizes, int n_in,
                              void* d_out, int out_size) {
    const float* X     = (const float*)d_in[0];
    const float* W1    = (const float*)d_in[1];
    const float* b1    = (const float*)d_in[2];
    const float* gamma = (const float*)d_in[3];
    const float* beta  = (const float*)d_in[4];
    const float* rmean = (const float*)d_in[5];
    const float* rvar  = (const float*)d_in[6];
    const float* W2    = (const float*)d_in[7];
    const float* b2    = (const float*)d_in[8];
    const float* We    = (const float*)d_in[9];

    float* out = (float*)d_out;                    // [N, A]
    float* ret = out + (size_t)NN * AA;            // [N, E]

    size_t smem = SMEM_FLOATS * sizeof(float);
    static bool attr_set = false;
    if (!attr_set) {
        cudaFuncSetAttribute(moe_fused, cudaFuncAttributeMaxDynamicSharedMemorySize, (int)smem);
        attr_set = true;
    }
    moe_fused<<<GRID, 128, smem>>>(X, W1, b1, gamma, beta, rmean, rvar, W2, b2, We, out, ret);
}